// round 15
// baseline (speedup 1.0000x reference)
#include <cuda_runtime.h>
#include <cuda_bf16.h>
#include <cuda_fp16.h>
#include <cstdint>

#define DM    1024
#define NH    16
#define BATCH 2
#define SEQ   2048
#define MTOT  (BATCH*SEQ)          // 4096
#define MD    ((size_t)MTOT * DM)  // 4194304

typedef unsigned short u16;

// ================= scratch (device globals, 16-bit raw storage) =================
__device__ u16 g_W [4u * DM * DM];    // fp16 single: Wq,Wk,Wv repacked [n][d], Wo^T
__device__ u16 g_X [3u * MTOT * DM];  // inputs fp16 single
__device__ u16 g_Ph[3u * MTOT * DM];  // QW,KW: fp16 hi ; VW: fp16 single
__device__ u16 g_Pl[3u * MTOT * DM];  // QW,KW: fp16 lo
__device__ u16 g_C [MTOT * (size_t)DM]; // ctx fp16 single

// ================= helpers =================
__device__ __forceinline__ uint32_t smem_u32(const void* p) {
    uint32_t a;
    asm("{ .reg .u64 t; cvta.to.shared.u64 t, %1; cvt.u32.u64 %0, t; }" : "=r"(a) : "l"(p));
    return a;
}
__device__ __forceinline__ void cp16(uint32_t dst, const void* src) {
    asm volatile("cp.async.cg.shared.global [%0], [%1], 16;" :: "r"(dst), "l"(src));
}
#define CP_COMMIT() asm volatile("cp.async.commit_group;" ::: "memory")
#define CP_WAIT2()  asm volatile("cp.async.wait_group 2;"  ::: "memory")
#define CP_WAIT1()  asm volatile("cp.async.wait_group 1;"  ::: "memory")
#define CP_WAIT0()  asm volatile("cp.async.wait_group 0;"  ::: "memory")

__device__ __forceinline__ void ldsm4(uint32_t r[4], uint32_t addr) {
    asm volatile("ldmatrix.sync.aligned.m8n8.x4.shared.b16 {%0,%1,%2,%3}, [%4];"
        : "=r"(r[0]), "=r"(r[1]), "=r"(r[2]), "=r"(r[3]) : "r"(addr));
}
__device__ __forceinline__ void ldsm4t(uint32_t r[4], uint32_t addr) {
    asm volatile("ldmatrix.sync.aligned.m8n8.x4.trans.shared.b16 {%0,%1,%2,%3}, [%4];"
        : "=r"(r[0]), "=r"(r[1]), "=r"(r[2]), "=r"(r[3]) : "r"(addr));
}
__device__ __forceinline__ void mma_h(float c[4], const uint32_t a[4], const uint32_t b[2]) {
    asm volatile("mma.sync.aligned.m16n8k16.row.col.f32.f16.f16.f32 "
        "{%0,%1,%2,%3}, {%4,%5,%6,%7}, {%8,%9}, {%0,%1,%2,%3};"
        : "+f"(c[0]), "+f"(c[1]), "+f"(c[2]), "+f"(c[3])
        : "r"(a[0]), "r"(a[1]), "r"(a[2]), "r"(a[3]), "r"(b[0]), "r"(b[1]));
}

__device__ __forceinline__ void fsplit_h(float v, u16& h, u16& l) {
    __half hh = __float2half_rn(v);
    float r = v - __half2float(hh);
    h = __half_as_ushort(hh);
    l = __half_as_ushort(__float2half_rn(r));
}
__device__ __forceinline__ void split_pack_h(float a, float b, uint32_t& hp, uint32_t& lp) {
    u16 ha, la, hb, lb;
    fsplit_h(a, ha, la); fsplit_h(b, hb, lb);
    hp = (uint32_t)ha | ((uint32_t)hb << 16);
    lp = (uint32_t)la | ((uint32_t)lb << 16);
}
__device__ __forceinline__ uint32_t pack_h2(float a, float b) {
    __half2 h = __floats2half2_rn(a, b);    // lo = a, hi = b
    return *(uint32_t*)&h;
}

// ================= conversion kernels =================
__global__ void cvt_h3(const float4* __restrict__ Q, const float4* __restrict__ K,
                       const float4* __restrict__ V) {
    const int i = blockIdx.x * 256 + threadIdx.x;       // over MD/4
    const size_t q4 = MD / 4;
    uint2* h = (uint2*)g_X;
    const float4* src[3] = {Q, K, V};
    #pragma unroll
    for (int a = 0; a < 3; ++a) {
        float4 v = src[a][i];
        h[a * q4 + i] = make_uint2(pack_h2(v.x, v.y), pack_h2(v.z, v.w));
    }
}

// merged repack: z<16 -> Wq/Wk/Wv head z ; z>=16 -> Wo transpose
__global__ void repack_all(const float* __restrict__ Wq, const float* __restrict__ Wk,
                           const float* __restrict__ Wv, const float* __restrict__ Wo) {
    __shared__ float tq[32][33], tk[32][33], tv[32][33];
    const int tx = threadIdx.x, ty = threadIdx.y;       // 32 x 8
    const int z = blockIdx.z;
    if (z < 16) {
        const int k0 = blockIdx.x * 32;
        const int d0 = blockIdx.y * 32;
        const int hh = z;
        #pragma unroll
        for (int i = 0; i < 4; ++i) {
            const int d = d0 + ty + i * 8;
            const size_t src = (size_t)hh * 65536 + (size_t)d * 64 + k0 + tx;
            tq[ty + i * 8][tx] = Wq[src];
            tk[ty + i * 8][tx] = Wk[src];
            tv[ty + i * 8][tx] = Wv[src];
        }
        __syncthreads();
        #pragma unroll
        for (int i = 0; i < 4; ++i) {
            const int k = k0 + ty + i * 8;
            const size_t dst = (size_t)(hh * 64 + k) * DM + d0 + tx;
            g_W[dst]            = __half_as_ushort(__float2half_rn(tq[tx][ty + i * 8]));
            g_W[dst + DM*DM]    = __half_as_ushort(__float2half_rn(tk[tx][ty + i * 8]));
            g_W[dst + 2*DM*DM]  = __half_as_ushort(__float2half_rn(tv[tx][ty + i * 8]));
        }
    } else {
        const int bx = ((z - 16) * 2 + blockIdx.x) * 32;   // 0..992
        const int by = blockIdx.y * 32;
        #pragma unroll
        for (int i = 0; i < 4; ++i)
            tq[ty + i * 8][tx] = Wo[(size_t)(by + ty + i * 8) * DM + bx + tx];
        __syncthreads();
        #pragma unroll
        for (int i = 0; i < 4; ++i) {
            size_t dst = 3u * DM * DM + (size_t)(bx + ty + i * 8) * DM + by + tx;
            g_W[dst] = __half_as_ushort(__float2half_rn(tq[tx][ty + i * 8]));
        }
    }
}

// ================= GEMM: single-term fp16; 8 warps, warp tile 32x64; deferred wait ======
#define GROW  128                // bytes per row (64 fp16)
#define GTILE (128*GROW)         // 16384
#define GSTG  (2*GTILE)          // 32768 per stage (A, W)
#define GSM   (3*GSTG)           // 98304, 3 stages -> 2 CTAs/SM
#define GNIT  (DM/64)            // 16

__device__ __forceinline__ uint32_t gswz(int row, int chunk) {   // chunk in 16B units, 0..7
    return (uint32_t)(row * GROW + ((chunk ^ (row & 7)) * 16));
}

__global__ __launch_bounds__(256, 2) void gemm_mma(
    const u16* __restrict__ AB, const u16* __restrict__ WB,
    const float* __restrict__ b0p, const float* __restrict__ b1p, const float* __restrict__ b2p,
    float* __restrict__ Cf, u16* __restrict__ ChB, u16* __restrict__ ClB,
    int mode)   // 0: fp32 out; 1: per-z (z<2 split 2-digit, z=2 single)
{
    extern __shared__ char sm[];
    const uint32_t sb = smem_u32(sm);
    const int t = threadIdx.x, lane = t & 31, wid = t >> 5;
    const int wm = wid & 3, wn = wid >> 2;        // 4m x 2n of 32x64
    const int m0 = blockIdx.y * 128, n0 = blockIdx.x * 128;
    const int z = blockIdx.z;

    const u16* A = AB + (size_t)z * MD;
    const u16* W = WB + (size_t)z * DM * DM;
    const float* bias = (z == 0) ? b0p : (z == 1) ? b1p : b2p;
    u16* Ch = ChB + (size_t)z * MD;
    u16* Cl = ClB + (size_t)z * MD;

    float c[2][8][4];
    #pragma unroll
    for (int i = 0; i < 2; i++)
        #pragma unroll
        for (int j = 0; j < 8; j++)
            #pragma unroll
            for (int k = 0; k < 4; k++) c[i][j][k] = 0.f;

    const int lrow = t >> 1, lhf = t & 1;
    const size_t gA = (size_t)(m0 + lrow) * DM;
    const size_t gB = (size_t)(n0 + lrow) * DM;

    auto LOAD = [&](int s, int k0) {
        uint32_t d = sb + s * GSTG;
        #pragma unroll
        for (int i = 0; i < 4; ++i) {
            const int ch = 4 * lhf + i;
            cp16(d + gswz(lrow, ch),         A + gA + k0 + ch * 8);
            cp16(d + GTILE + gswz(lrow, ch), W + gB + k0 + ch * 8);
        }
    };

    LOAD(0, 0);  CP_COMMIT();
    LOAD(1, 64); CP_COMMIT();

    const int arow = wm * 32 + ((lane >> 3) & 1) * 8 + (lane & 7);
    const int ach  = (lane >> 4);
    const int brow = wn * 64 + (lane >> 4) * 8 + (lane & 7);
    const int bch  = (lane >> 3) & 1;

    int slot = 0;
    for (int it = 0; it < GNIT; ++it) {
        __syncthreads();
        if (it + 2 < GNIT) LOAD((it + 2) % 3, (it + 2) * 64);
        CP_COMMIT();
        CP_WAIT2();                 // oldest (current) stage completed
        const uint32_t tb = sb + slot * GSTG;
        slot = (slot == 2) ? 0 : slot + 1;
        #pragma unroll
        for (int ks = 0; ks < 4; ++ks) {
            uint32_t bh[8][2];
            #pragma unroll
            for (int np = 0; np < 4; ++np) {
                uint32_t r[4];
                ldsm4(r, tb + GTILE + gswz(brow + np * 16, ks * 2 + bch));
                bh[2*np][0] = r[0]; bh[2*np][1] = r[1]; bh[2*np+1][0] = r[2]; bh[2*np+1][1] = r[3];
            }
            uint32_t ah[2][4];
            #pragma unroll
            for (int mt = 0; mt < 2; ++mt)
                ldsm4(ah[mt], tb + gswz(arow + mt * 16, ks * 2 + ach));
            #pragma unroll
            for (int mt = 0; mt < 2; ++mt)
                #pragma unroll
                for (int nt = 0; nt < 8; ++nt) mma_h(c[mt][nt], ah[mt], bh[nt]);
        }
    }

    #pragma unroll
    for (int mt = 0; mt < 2; ++mt) {
        const int r0 = m0 + wm * 32 + mt * 16 + (lane >> 2);
        #pragma unroll
        for (int nt = 0; nt < 8; ++nt) {
            const int col = n0 + wn * 64 + nt * 8 + (lane & 3) * 2;
            const float bx = bias[col], by = bias[col + 1];
            float v00 = c[mt][nt][0] + bx, v01 = c[mt][nt][1] + by;
            float v10 = c[mt][nt][2] + bx, v11 = c[mt][nt][3] + by;
            if (!mode) {
                *(float2*)(Cf + (size_t)r0 * DM + col)       = make_float2(v00, v01);
                *(float2*)(Cf + (size_t)(r0 + 8) * DM + col) = make_float2(v10, v11);
            } else if (z < 2) {
                uint32_t hp, lp;
                split_pack_h(v00, v01, hp, lp);
                *(uint32_t*)(Ch + (size_t)r0 * DM + col) = hp;
                *(uint32_t*)(Cl + (size_t)r0 * DM + col) = lp;
                split_pack_h(v10, v11, hp, lp);
                *(uint32_t*)(Ch + (size_t)(r0 + 8) * DM + col) = hp;
                *(uint32_t*)(Cl + (size_t)(r0 + 8) * DM + col) = lp;
            } else {
                *(uint32_t*)(Ch + (size_t)r0 * DM + col)       = pack_h2(v00, v01);
                *(uint32_t*)(Ch + (size_t)(r0 + 8) * DM + col) = pack_h2(v10, v11);
            }
        }
    }
}

// ================= flash: 128 q/CTA, 256 thr; 3-stage single-sync pipeline =================
#define FROW  144                // 128B data + 16B pad
#define FTILE (64*FROW)          // 9216
#define FSTG  (3*FTILE)          // 27648 per stage (Kh,Kl,V)
#define FSM   (3*FSTG)           // 82944 -> 2 CTAs/SM (reg-bound)
#define FNIT  (SEQ/64)           // 32
#define L2E   1.4426950408889634f

__global__ __launch_bounds__(256, 2) void flash_mma()
{
    extern __shared__ char sm[];
    const uint32_t sb = smem_u32(sm);
    const int t = threadIdx.x, lane = t & 31, wid = t >> 5;   // wid 0..7
    const int qt = blockIdx.x, h = blockIdx.y, b = blockIdx.z;
    const size_t rowBase = (size_t)b * SEQ;
    const int q0 = qt * 128;

    const u16* qw_h = g_Ph;
    const u16* qw_l = g_Pl;
    const u16* kw_h = g_Ph + MD;
    const u16* kw_l = g_Pl + MD;
    const u16* vw   = g_Ph + 2 * MD;   // fp16 single

    // ---- stage Q (128 x 64, fp16 hi+lo), pull fragments ----
    {
        const int row = t >> 1, hf = t & 1;
        const size_t src = (rowBase + q0 + row) * DM + h * 64 + hf * 32;
        const uint32_t d0 = sb + row * FROW + hf * 64;
        #pragma unroll
        for (int i = 0; i < 4; i++) {
            cp16(d0 + i * 16,              qw_h + src + i * 8);
            cp16(d0 + 128 * FROW + i * 16, qw_l + src + i * 8);
        }
    }
    CP_COMMIT(); CP_WAIT0();
    __syncthreads();

    uint32_t qh[4][4], ql[4][4];
    {
        const int qrow = wid * 16 + ((lane >> 3) & 1) * 8 + (lane & 7);
        const int qch  = lane >> 4;
        #pragma unroll
        for (int kt = 0; kt < 4; ++kt) {
            uint32_t ad = sb + qrow * FROW + (kt * 2 + qch) * 16;
            ldsm4(qh[kt], ad);
            ldsm4(ql[kt], ad + 128 * FROW);
        }
    }
    __syncthreads();

    const int lrow = t >> 2, lq = t & 3;
    const uint32_t ldst = sb + lrow * FROW + lq * 32;
    auto LOADKV = [&](int s, int kt0) {
        const size_t src = (rowBase + kt0 + lrow) * DM + h * 64 + lq * 16;
        uint32_t d = ldst + s * FSTG;
        cp16(d,                   kw_h + src); cp16(d + 16,             kw_h + src + 8);
        cp16(d + FTILE,           kw_l + src); cp16(d + FTILE + 16,     kw_l + src + 8);
        cp16(d + 2*FTILE,         vw   + src); cp16(d + 2*FTILE + 16,   vw   + src + 8);
    };
    LOADKV(0, 0);  CP_COMMIT();
    LOADKV(1, 64); CP_COMMIT();

    float o[8][4];
    #pragma unroll
    for (int i = 0; i < 8; i++)
        #pragma unroll
        for (int j = 0; j < 4; j++) o[i][j] = 0.f;
    float M0 = -1e30f, M1 = -1e30f, l0 = 0.f, l1 = 0.f;

    const int kbrow = (lane >> 4) * 8 + (lane & 7);
    const int kbch  = (lane >> 3) & 1;
    const int vrow  = ((lane >> 3) & 1) * 8 + (lane & 7);
    const int vch   = lane >> 4;

    int slot = 0;
    for (int it = 0; it < FNIT; ++it) {
        __syncthreads();
        if (it + 2 < FNIT) LOADKV((it + 2) % 3, (it + 2) * 64);
        CP_COMMIT();
        CP_WAIT2();                 // current stage ready
        const uint32_t tb = sb + slot * FSTG;
        slot = (slot == 2) ? 0 : slot + 1;

        // ---- scores S = Q K^T (fp16 3-term), term-major ----
        float sc[8][4];
        #pragma unroll
        for (int i = 0; i < 8; i++)
            #pragma unroll
            for (int j = 0; j < 4; j++) sc[i][j] = 0.f;

        #pragma unroll
        for (int kd = 0; kd < 4; ++kd) {
            uint32_t RH[4][4], RL[4][4];
            #pragma unroll
            for (int np = 0; np < 4; ++np) {
                uint32_t ad = tb + (np * 16 + kbrow) * FROW + (kd * 2 + kbch) * 16;
                ldsm4(RH[np], ad);
                ldsm4(RL[np], ad + FTILE);
            }
            #pragma unroll
            for (int np = 0; np < 4; ++np) {
                mma_h(sc[2*np],   qh[kd], RH[np]);
                mma_h(sc[2*np+1], qh[kd], RH[np] + 2);
            }
            #pragma unroll
            for (int np = 0; np < 4; ++np) {
                mma_h(sc[2*np],   qh[kd], RL[np]);
                mma_h(sc[2*np+1], qh[kd], RL[np] + 2);
            }
            #pragma unroll
            for (int np = 0; np < 4; ++np) {
                mma_h(sc[2*np],   ql[kd], RH[np]);
                mma_h(sc[2*np+1], ql[kd], RH[np] + 2);
            }
        }

        // ---- online max: p = exp(s - M) in (0,1] fits fp16 exactly ----
        float tm0 = -1e30f, tm1 = -1e30f;
        #pragma unroll
        for (int nt = 0; nt < 8; ++nt) {
            tm0 = fmaxf(tm0, fmaxf(sc[nt][0], sc[nt][1]));
            tm1 = fmaxf(tm1, fmaxf(sc[nt][2], sc[nt][3]));
        }
        tm0 = fmaxf(tm0, __shfl_xor_sync(0xffffffffu, tm0, 1));
        tm0 = fmaxf(tm0, __shfl_xor_sync(0xffffffffu, tm0, 2));
        tm1 = fmaxf(tm1, __shfl_xor_sync(0xffffffffu, tm1, 1));
        tm1 = fmaxf(tm1, __shfl_xor_sync(0xffffffffu, tm1, 2));
        const float Mn0 = fmaxf(M0, tm0), Mn1 = fmaxf(M1, tm1);
        const float s0 = exp2f((M0 - Mn0) * L2E), s1 = exp2f((M1 - Mn1) * L2E);
        M0 = Mn0; M1 = Mn1;
        #pragma unroll
        for (int nt = 0; nt < 8; ++nt) {
            o[nt][0] *= s0; o[nt][1] *= s0; o[nt][2] *= s1; o[nt][3] *= s1;
        }

        float rs0 = 0.f, rs1 = 0.f;
        #pragma unroll
        for (int nt = 0; nt < 8; ++nt) {
            float p0 = exp2f((sc[nt][0] - Mn0) * L2E);
            float p1 = exp2f((sc[nt][1] - Mn0) * L2E);
            float p2 = exp2f((sc[nt][2] - Mn1) * L2E);
            float p3 = exp2f((sc[nt][3] - Mn1) * L2E);
            sc[nt][0] = p0; sc[nt][1] = p1; sc[nt][2] = p2; sc[nt][3] = p3;
            rs0 += p0 + p1; rs1 += p2 + p3;
        }
        l0 = l0 * s0 + rs0;
        l1 = l1 * s1 + rs1;

        // ---- P fragments (fp16 single) ----
        uint32_t pa[4][4];
        #pragma unroll
        for (int j = 0; j < 4; ++j) {
            pa[j][0] = pack_h2(sc[2*j][0],   sc[2*j][1]);
            pa[j][1] = pack_h2(sc[2*j][2],   sc[2*j][3]);
            pa[j][2] = pack_h2(sc[2*j+1][0], sc[2*j+1][1]);
            pa[j][3] = pack_h2(sc[2*j+1][2], sc[2*j+1][3]);
        }

        // ---- O += P V (single fp16 term) ----
        #pragma unroll
        for (int j = 0; j < 4; ++j) {
            uint32_t VH[4][4];
            #pragma unroll
            for (int np = 0; np < 4; ++np) {
                uint32_t ad = tb + 2 * FTILE + (j * 16 + vrow) * FROW + (np * 2 + vch) * 16;
                ldsm4t(VH[np], ad);
            }
            #pragma unroll
            for (int np = 0; np < 4; ++np) {
                mma_h(o[2*np],   pa[j], VH[np]);
                mma_h(o[2*np+1], pa[j], VH[np] + 2);
            }
        }
    }

    // ---- final quad reduction + normalize; emit ctx fp16 single ----
    l0 += __shfl_xor_sync(0xffffffffu, l0, 1);
    l0 += __shfl_xor_sync(0xffffffffu, l0, 2);
    l1 += __shfl_xor_sync(0xffffffffu, l1, 1);
    l1 += __shfl_xor_sync(0xffffffffu, l1, 2);
    const float i0 = 1.0f / (l0 * 128.0f);
    const float i1 = 1.0f / (l1 * 128.0f);
    const int row0 = (int)rowBase + q0 + wid * 16 + (lane >> 2);
    const size_t base0 = (size_t)row0 * DM + h * 64 + (lane & 3) * 2;
    #pragma unroll
    for (int nt = 0; nt < 8; ++nt) {
        *(uint32_t*)(g_C + base0 + nt * 8)          = pack_h2(o[nt][0] * i0, o[nt][1] * i0);
        *(uint32_t*)(g_C + base0 + 8 * DM + nt * 8) = pack_h2(o[nt][2] * i1, o[nt][3] * i1);
    }
}

// ================= launcher =================
extern "C" void kernel_launch(void* const* d_in, const int* in_sizes, int n_in,
                              void* d_out, int out_size)
{
    const float* Q  = (const float*)d_in[0];
    const float* K  = (const float*)d_in[1];
    const float* V  = (const float*)d_in[2];
    const float* Wq = (const float*)d_in[3];
    const float* bq = (const float*)d_in[4];
    const float* Wk = (const float*)d_in[5];
    const float* bk = (const float*)d_in[6];
    const float* Wv = (const float*)d_in[7];
    const float* bv = (const float*)d_in[8];
    const float* Wo = (const float*)d_in[9];
    const float* bo = (const float*)d_in[10];
    float* out = (float*)d_out;
    (void)in_sizes; (void)n_in; (void)out_size;

    cudaFuncSetAttribute(gemm_mma,  cudaFuncAttributeMaxDynamicSharedMemorySize, GSM);
    cudaFuncSetAttribute(flash_mma, cudaFuncAttributeMaxDynamicSharedMemorySize, FSM);

    u16 *w, *x, *ph, *pl, *cc;
    cudaGetSymbolAddress((void**)&w,  g_W);
    cudaGetSymbolAddress((void**)&x,  g_X);
    cudaGetSymbolAddress((void**)&ph, g_Ph);
    cudaGetSymbolAddress((void**)&pl, g_Pl);
    cudaGetSymbolAddress((void**)&cc, g_C);

    cvt_h3<<<(int)(MD / (256 * 4)), 256>>>((const float4*)Q, (const float4*)K, (const float4*)V);
    repack_all<<<dim3(2, 32, 32), dim3(32, 8)>>>(Wq, Wk, Wv, Wo);

    // fused 3-way projection GEMM (single-term fp16): z selects Q/K/V
    gemm_mma<<<dim3(DM / 128, MTOT / 128, 3), 256, GSM>>>(
        x, w, bq, bk, bv, nullptr, ph, pl, 1);

    flash_mma<<<dim3(SEQ / 128, NH, BATCH), 256, FSM>>>();

    // output projection (single-term fp16, fp32 out)
    gemm_mma<<<dim3(DM / 128, MTOT / 128, 1), 256, GSM>>>(
        cc, w + 3u * DM * DM, bo, bo, bo, out, nullptr, nullptr, 0);
}

// round 16
// speedup vs baseline: 1.0457x; 1.0457x over previous
#include <cuda_runtime.h>
#include <cuda_bf16.h>
#include <cuda_fp16.h>
#include <cstdint>

#define DM    1024
#define NH    16
#define BATCH 2
#define SEQ   2048
#define MTOT  (BATCH*SEQ)          // 4096
#define MD    ((size_t)MTOT * DM)  // 4194304

typedef unsigned short u16;

// ================= scratch (device globals, 16-bit raw storage) =================
__device__ u16 g_W [4u * DM * DM];    // fp16 single: Wq,Wk,Wv repacked [n][d], Wo^T
__device__ u16 g_X [3u * MTOT * DM];  // inputs fp16 single
__device__ u16 g_Ph[3u * MTOT * DM];  // QW,KW: fp16 hi ; VW: fp16 single
__device__ u16 g_Pl[3u * MTOT * DM];  // QW,KW: fp16 lo
__device__ u16 g_C [MTOT * (size_t)DM]; // ctx fp16 single

// ================= helpers =================
__device__ __forceinline__ uint32_t smem_u32(const void* p) {
    uint32_t a;
    asm("{ .reg .u64 t; cvta.to.shared.u64 t, %1; cvt.u32.u64 %0, t; }" : "=r"(a) : "l"(p));
    return a;
}
__device__ __forceinline__ void cp16(uint32_t dst, const void* src) {
    asm volatile("cp.async.cg.shared.global [%0], [%1], 16;" :: "r"(dst), "l"(src));
}
#define CP_COMMIT() asm volatile("cp.async.commit_group;" ::: "memory")
#define CP_WAIT1()  asm volatile("cp.async.wait_group 1;"  ::: "memory")
#define CP_WAIT0()  asm volatile("cp.async.wait_group 0;"  ::: "memory")

__device__ __forceinline__ void ldsm4(uint32_t r[4], uint32_t addr) {
    asm volatile("ldmatrix.sync.aligned.m8n8.x4.shared.b16 {%0,%1,%2,%3}, [%4];"
        : "=r"(r[0]), "=r"(r[1]), "=r"(r[2]), "=r"(r[3]) : "r"(addr));
}
__device__ __forceinline__ void ldsm4t(uint32_t r[4], uint32_t addr) {
    asm volatile("ldmatrix.sync.aligned.m8n8.x4.trans.shared.b16 {%0,%1,%2,%3}, [%4];"
        : "=r"(r[0]), "=r"(r[1]), "=r"(r[2]), "=r"(r[3]) : "r"(addr));
}
__device__ __forceinline__ void mma_h(float c[4], const uint32_t a[4], const uint32_t b[2]) {
    asm volatile("mma.sync.aligned.m16n8k16.row.col.f32.f16.f16.f32 "
        "{%0,%1,%2,%3}, {%4,%5,%6,%7}, {%8,%9}, {%0,%1,%2,%3};"
        : "+f"(c[0]), "+f"(c[1]), "+f"(c[2]), "+f"(c[3])
        : "r"(a[0]), "r"(a[1]), "r"(a[2]), "r"(a[3]), "r"(b[0]), "r"(b[1]));
}

__device__ __forceinline__ void fsplit_h(float v, u16& h, u16& l) {
    __half hh = __float2half_rn(v);
    float r = v - __half2float(hh);
    h = __half_as_ushort(hh);
    l = __half_as_ushort(__float2half_rn(r));
}
__device__ __forceinline__ void split_pack_h(float a, float b, uint32_t& hp, uint32_t& lp) {
    u16 ha, la, hb, lb;
    fsplit_h(a, ha, la); fsplit_h(b, hb, lb);
    hp = (uint32_t)ha | ((uint32_t)hb << 16);
    lp = (uint32_t)la | ((uint32_t)lb << 16);
}
__device__ __forceinline__ uint32_t pack_h2(float a, float b) {
    __half2 h = __floats2half2_rn(a, b);    // lo = a, hi = b
    return *(uint32_t*)&h;
}
// packed fp16x2 2^x
__device__ __forceinline__ uint32_t h2exp2(uint32_t x) {
    uint32_t r;
    asm("ex2.approx.f16x2 %0, %1;" : "=r"(r) : "r"(x));
    return r;
}

// ================= conversion kernels =================
__global__ void cvt_h3(const float4* __restrict__ Q, const float4* __restrict__ K,
                       const float4* __restrict__ V) {
    const int i = blockIdx.x * 256 + threadIdx.x;       // over MD/4
    const size_t q4 = MD / 4;
    uint2* h = (uint2*)g_X;
    const float4* src[3] = {Q, K, V};
    #pragma unroll
    for (int a = 0; a < 3; ++a) {
        float4 v = src[a][i];
        h[a * q4 + i] = make_uint2(pack_h2(v.x, v.y), pack_h2(v.z, v.w));
    }
}

// merged repack: z<16 -> Wq/Wk/Wv head z ; z>=16 -> Wo transpose
__global__ void repack_all(const float* __restrict__ Wq, const float* __restrict__ Wk,
                           const float* __restrict__ Wv, const float* __restrict__ Wo) {
    __shared__ float tq[32][33], tk[32][33], tv[32][33];
    const int tx = threadIdx.x, ty = threadIdx.y;       // 32 x 8
    const int z = blockIdx.z;
    if (z < 16) {
        const int k0 = blockIdx.x * 32;
        const int d0 = blockIdx.y * 32;
        const int hh = z;
        #pragma unroll
        for (int i = 0; i < 4; ++i) {
            const int d = d0 + ty + i * 8;
            const size_t src = (size_t)hh * 65536 + (size_t)d * 64 + k0 + tx;
            tq[ty + i * 8][tx] = Wq[src];
            tk[ty + i * 8][tx] = Wk[src];
            tv[ty + i * 8][tx] = Wv[src];
        }
        __syncthreads();
        #pragma unroll
        for (int i = 0; i < 4; ++i) {
            const int k = k0 + ty + i * 8;
            const size_t dst = (size_t)(hh * 64 + k) * DM + d0 + tx;
            g_W[dst]            = __half_as_ushort(__float2half_rn(tq[tx][ty + i * 8]));
            g_W[dst + DM*DM]    = __half_as_ushort(__float2half_rn(tk[tx][ty + i * 8]));
            g_W[dst + 2*DM*DM]  = __half_as_ushort(__float2half_rn(tv[tx][ty + i * 8]));
        }
    } else {
        const int bx = ((z - 16) * 2 + blockIdx.x) * 32;   // 0..992
        const int by = blockIdx.y * 32;
        #pragma unroll
        for (int i = 0; i < 4; ++i)
            tq[ty + i * 8][tx] = Wo[(size_t)(by + ty + i * 8) * DM + bx + tx];
        __syncthreads();
        #pragma unroll
        for (int i = 0; i < 4; ++i) {
            size_t dst = 3u * DM * DM + (size_t)(bx + ty + i * 8) * DM + by + tx;
            g_W[dst] = __half_as_ushort(__float2half_rn(tq[tx][ty + i * 8]));
        }
    }
}

// ================= GEMM: single-term fp16; 8 warps, warp tile 32x64 (R14 config) ======
#define GROW  128                // bytes per row (64 fp16)
#define GTILE (128*GROW)         // 16384
#define GSTG  (2*GTILE)          // 32768 per stage (A, W)
#define GSM   (3*GSTG)           // 98304, 3 stages -> 2 CTAs/SM
#define GNIT  (DM/64)            // 16

__device__ __forceinline__ uint32_t gswz(int row, int chunk) {   // chunk in 16B units, 0..7
    return (uint32_t)(row * GROW + ((chunk ^ (row & 7)) * 16));
}

__global__ __launch_bounds__(256, 2) void gemm_mma(
    const u16* __restrict__ AB, const u16* __restrict__ WB,
    const float* __restrict__ b0p, const float* __restrict__ b1p, const float* __restrict__ b2p,
    float* __restrict__ Cf, u16* __restrict__ ChB, u16* __restrict__ ClB,
    int mode)   // 0: fp32 out; 1: per-z (z<2 split 2-digit, z=2 single)
{
    extern __shared__ char sm[];
    const uint32_t sb = smem_u32(sm);
    const int t = threadIdx.x, lane = t & 31, wid = t >> 5;
    const int wm = wid & 3, wn = wid >> 2;        // 4m x 2n of 32x64
    const int m0 = blockIdx.y * 128, n0 = blockIdx.x * 128;
    const int z = blockIdx.z;

    const u16* A = AB + (size_t)z * MD;
    const u16* W = WB + (size_t)z * DM * DM;
    const float* bias = (z == 0) ? b0p : (z == 1) ? b1p : b2p;
    u16* Ch = ChB + (size_t)z * MD;
    u16* Cl = ClB + (size_t)z * MD;

    float c[2][8][4];
    #pragma unroll
    for (int i = 0; i < 2; i++)
        #pragma unroll
        for (int j = 0; j < 8; j++)
            #pragma unroll
            for (int k = 0; k < 4; k++) c[i][j][k] = 0.f;

    const int lrow = t >> 1, lhf = t & 1;
    const size_t gA = (size_t)(m0 + lrow) * DM;
    const size_t gB = (size_t)(n0 + lrow) * DM;

    auto LOAD = [&](int s, int k0) {
        uint32_t d = sb + s * GSTG;
        #pragma unroll
        for (int i = 0; i < 4; ++i) {
            const int ch = 4 * lhf + i;
            cp16(d + gswz(lrow, ch),         A + gA + k0 + ch * 8);
            cp16(d + GTILE + gswz(lrow, ch), W + gB + k0 + ch * 8);
        }
    };

    LOAD(0, 0);  CP_COMMIT();
    LOAD(1, 64); CP_COMMIT();

    const int arow = wm * 32 + ((lane >> 3) & 1) * 8 + (lane & 7);
    const int ach  = (lane >> 4);
    const int brow = wn * 64 + (lane >> 4) * 8 + (lane & 7);
    const int bch  = (lane >> 3) & 1;

    int slot = 0;
    for (int it = 0; it < GNIT; ++it) {
        CP_WAIT1();
        __syncthreads();
        if (it + 2 < GNIT) LOAD((it + 2) % 3, (it + 2) * 64);
        CP_COMMIT();
        const uint32_t tb = sb + slot * GSTG;
        slot = (slot == 2) ? 0 : slot + 1;
        #pragma unroll
        for (int ks = 0; ks < 4; ++ks) {
            uint32_t bh[8][2];
            #pragma unroll
            for (int np = 0; np < 4; ++np) {
                uint32_t r[4];
                ldsm4(r, tb + GTILE + gswz(brow + np * 16, ks * 2 + bch));
                bh[2*np][0] = r[0]; bh[2*np][1] = r[1]; bh[2*np+1][0] = r[2]; bh[2*np+1][1] = r[3];
            }
            uint32_t ah[2][4];
            #pragma unroll
            for (int mt = 0; mt < 2; ++mt)
                ldsm4(ah[mt], tb + gswz(arow + mt * 16, ks * 2 + ach));
            #pragma unroll
            for (int mt = 0; mt < 2; ++mt)
                #pragma unroll
                for (int nt = 0; nt < 8; ++nt) mma_h(c[mt][nt], ah[mt], bh[nt]);
        }
    }

    #pragma unroll
    for (int mt = 0; mt < 2; ++mt) {
        const int r0 = m0 + wm * 32 + mt * 16 + (lane >> 2);
        #pragma unroll
        for (int nt = 0; nt < 8; ++nt) {
            const int col = n0 + wn * 64 + nt * 8 + (lane & 3) * 2;
            const float bx = bias[col], by = bias[col + 1];
            float v00 = c[mt][nt][0] + bx, v01 = c[mt][nt][1] + by;
            float v10 = c[mt][nt][2] + bx, v11 = c[mt][nt][3] + by;
            if (!mode) {
                *(float2*)(Cf + (size_t)r0 * DM + col)       = make_float2(v00, v01);
                *(float2*)(Cf + (size_t)(r0 + 8) * DM + col) = make_float2(v10, v11);
            } else if (z < 2) {
                uint32_t hp, lp;
                split_pack_h(v00, v01, hp, lp);
                *(uint32_t*)(Ch + (size_t)r0 * DM + col) = hp;
                *(uint32_t*)(Cl + (size_t)r0 * DM + col) = lp;
                split_pack_h(v10, v11, hp, lp);
                *(uint32_t*)(Ch + (size_t)(r0 + 8) * DM + col) = hp;
                *(uint32_t*)(Cl + (size_t)(r0 + 8) * DM + col) = lp;
            } else {
                *(uint32_t*)(Ch + (size_t)r0 * DM + col)       = pack_h2(v00, v01);
                *(uint32_t*)(Ch + (size_t)(r0 + 8) * DM + col) = pack_h2(v10, v11);
            }
        }
    }
}

// ================= flash: 128 q/CTA; f16x2 exp, row-sum via ones-MMA =================
#define FROW  144                // 128B data + 16B pad
#define FTILE (64*FROW)          // 9216
#define FSTG  (3*FTILE)          // 27648 per stage (Kh,Kl,V)
#define FSM   (2*FSTG)           // 55296 (R14 2-stage config)
#define FNIT  (SEQ/64)           // 32
#define L2E   1.4426950408889634f

__global__ __launch_bounds__(256, 2) void flash_mma()
{
    extern __shared__ char sm[];
    const uint32_t sb = smem_u32(sm);
    const int t = threadIdx.x, lane = t & 31, wid = t >> 5;   // wid 0..7
    const int qt = blockIdx.x, h = blockIdx.y, b = blockIdx.z;
    const size_t rowBase = (size_t)b * SEQ;
    const int q0 = qt * 128;

    const u16* qw_h = g_Ph;
    const u16* qw_l = g_Pl;
    const u16* kw_h = g_Ph + MD;
    const u16* kw_l = g_Pl + MD;
    const u16* vw   = g_Ph + 2 * MD;   // fp16 single

    // ---- stage Q (128 x 64, fp16 hi+lo), pull fragments ----
    {
        const int row = t >> 1, hf = t & 1;
        const size_t src = (rowBase + q0 + row) * DM + h * 64 + hf * 32;
        const uint32_t d0 = sb + row * FROW + hf * 64;
        #pragma unroll
        for (int i = 0; i < 4; i++) {
            cp16(d0 + i * 16,              qw_h + src + i * 8);
            cp16(d0 + 128 * FROW + i * 16, qw_l + src + i * 8);
        }
    }
    CP_COMMIT(); CP_WAIT0();
    __syncthreads();

    uint32_t qh[4][4], ql[4][4];
    {
        const int qrow = wid * 16 + ((lane >> 3) & 1) * 8 + (lane & 7);
        const int qch  = lane >> 4;
        #pragma unroll
        for (int kt = 0; kt < 4; ++kt) {
            uint32_t ad = sb + qrow * FROW + (kt * 2 + qch) * 16;
            ldsm4(qh[kt], ad);
            ldsm4(ql[kt], ad + 128 * FROW);
        }
    }
    __syncthreads();

    const int lrow = t >> 2, lq = t & 3;
    const uint32_t ldst = sb + lrow * FROW + lq * 32;
    auto LOADKV = [&](int s, int kt0) {
        const size_t src = (rowBase + kt0 + lrow) * DM + h * 64 + lq * 16;
        uint32_t d = ldst + s * FSTG;
        cp16(d,                   kw_h + src); cp16(d + 16,             kw_h + src + 8);
        cp16(d + FTILE,           kw_l + src); cp16(d + FTILE + 16,     kw_l + src + 8);
        cp16(d + 2*FTILE,         vw   + src); cp16(d + 2*FTILE + 16,   vw   + src + 8);
    };
    LOADKV(0, 0);  CP_COMMIT();
    LOADKV(1, 64); CP_COMMIT();

    float o[8][4];
    #pragma unroll
    for (int i = 0; i < 8; i++)
        #pragma unroll
        for (int j = 0; j < 4; j++) o[i][j] = 0.f;
    float la[4] = {0.f, 0.f, 0.f, 0.f};    // row-sum accumulator (ones-MMA)
    float M0 = -1e30f, M1 = -1e30f;
    const uint32_t ones[2] = {0x3C003C00u, 0x3C003C00u};   // fp16 1.0 x4

    const int kbrow = (lane >> 4) * 8 + (lane & 7);
    const int kbch  = (lane >> 3) & 1;
    const int vrow  = ((lane >> 3) & 1) * 8 + (lane & 7);
    const int vch   = lane >> 4;

    for (int it = 0; it < FNIT; ++it) {
        CP_WAIT1();
        __syncthreads();
        const uint32_t tb = sb + (it & 1) * FSTG;

        // ---- scores S = Q K^T (fp16 3-term), term-major ----
        float sc[8][4];
        #pragma unroll
        for (int i = 0; i < 8; i++)
            #pragma unroll
            for (int j = 0; j < 4; j++) sc[i][j] = 0.f;

        #pragma unroll
        for (int kd = 0; kd < 4; ++kd) {
            uint32_t RH[4][4], RL[4][4];
            #pragma unroll
            for (int np = 0; np < 4; ++np) {
                uint32_t ad = tb + (np * 16 + kbrow) * FROW + (kd * 2 + kbch) * 16;
                ldsm4(RH[np], ad);
                ldsm4(RL[np], ad + FTILE);
            }
            #pragma unroll
            for (int np = 0; np < 4; ++np) {
                mma_h(sc[2*np],   qh[kd], RH[np]);
                mma_h(sc[2*np+1], qh[kd], RH[np] + 2);
            }
            #pragma unroll
            for (int np = 0; np < 4; ++np) {
                mma_h(sc[2*np],   qh[kd], RL[np]);
                mma_h(sc[2*np+1], qh[kd], RL[np] + 2);
            }
            #pragma unroll
            for (int np = 0; np < 4; ++np) {
                mma_h(sc[2*np],   ql[kd], RH[np]);
                mma_h(sc[2*np+1], ql[kd], RH[np] + 2);
            }
        }

        // ---- online max ----
        float tm0 = -1e30f, tm1 = -1e30f;
        #pragma unroll
        for (int nt = 0; nt < 8; ++nt) {
            tm0 = fmaxf(tm0, fmaxf(sc[nt][0], sc[nt][1]));
            tm1 = fmaxf(tm1, fmaxf(sc[nt][2], sc[nt][3]));
        }
        tm0 = fmaxf(tm0, __shfl_xor_sync(0xffffffffu, tm0, 1));
        tm0 = fmaxf(tm0, __shfl_xor_sync(0xffffffffu, tm0, 2));
        tm1 = fmaxf(tm1, __shfl_xor_sync(0xffffffffu, tm1, 1));
        tm1 = fmaxf(tm1, __shfl_xor_sync(0xffffffffu, tm1, 2));
        const float Mn0 = fmaxf(M0, tm0), Mn1 = fmaxf(M1, tm1);
        const float s0 = exp2f((M0 - Mn0) * L2E), s1 = exp2f((M1 - Mn1) * L2E);
        M0 = Mn0; M1 = Mn1;
        #pragma unroll
        for (int nt = 0; nt < 8; ++nt) {
            o[nt][0] *= s0; o[nt][1] *= s0; o[nt][2] *= s1; o[nt][3] *= s1;
        }
        la[0] *= s0; la[1] *= s0; la[2] *= s1; la[3] *= s1;

        // ---- P = 2^(s*L2E - M*L2E) via packed f16x2 exp (output = MMA fragment) ----
        const float c0 = Mn0 * L2E, c1 = Mn1 * L2E;
        uint32_t pa[4][4];
        #pragma unroll
        for (int j = 0; j < 4; ++j) {
            pa[j][0] = h2exp2(pack_h2(fmaf(sc[2*j][0],   L2E, -c0), fmaf(sc[2*j][1],   L2E, -c0)));
            pa[j][1] = h2exp2(pack_h2(fmaf(sc[2*j][2],   L2E, -c1), fmaf(sc[2*j][3],   L2E, -c1)));
            pa[j][2] = h2exp2(pack_h2(fmaf(sc[2*j+1][0], L2E, -c0), fmaf(sc[2*j+1][1], L2E, -c0)));
            pa[j][3] = h2exp2(pack_h2(fmaf(sc[2*j+1][2], L2E, -c1), fmaf(sc[2*j+1][3], L2E, -c1)));
        }

        // ---- row sums via ones-MMA (exactly consistent with fp16 P) ----
        #pragma unroll
        for (int j = 0; j < 4; ++j) mma_h(la, pa[j], ones);

        // ---- O += P V (single fp16 term) ----
        #pragma unroll
        for (int j = 0; j < 4; ++j) {
            uint32_t VH[4][4];
            #pragma unroll
            for (int np = 0; np < 4; ++np) {
                uint32_t ad = tb + 2 * FTILE + (j * 16 + vrow) * FROW + (np * 2 + vch) * 16;
                ldsm4t(VH[np], ad);
            }
            #pragma unroll
            for (int np = 0; np < 4; ++np) {
                mma_h(o[2*np],   pa[j], VH[np]);
                mma_h(o[2*np+1], pa[j], VH[np] + 2);
            }
        }

        __syncthreads();
        if (it + 2 < FNIT) LOADKV(it & 1, (it + 2) * 64);
        CP_COMMIT();
    }

    // ---- normalize (la already holds full row sums; no reduction needed) ----
    const float i0 = 1.0f / (la[0] * 128.0f);
    const float i1 = 1.0f / (la[2] * 128.0f);
    const int row0 = (int)rowBase + q0 + wid * 16 + (lane >> 2);
    const size_t base0 = (size_t)row0 * DM + h * 64 + (lane & 3) * 2;
    #pragma unroll
    for (int nt = 0; nt < 8; ++nt) {
        *(uint32_t*)(g_C + base0 + nt * 8)          = pack_h2(o[nt][0] * i0, o[nt][1] * i0);
        *(uint32_t*)(g_C + base0 + 8 * DM + nt * 8) = pack_h2(o[nt][2] * i1, o[nt][3] * i1);
    }
}

// ================= launcher =================
extern "C" void kernel_launch(void* const* d_in, const int* in_sizes, int n_in,
                              void* d_out, int out_size)
{
    const float* Q  = (const float*)d_in[0];
    const float* K  = (const float*)d_in[1];
    const float* V  = (const float*)d_in[2];
    const float* Wq = (const float*)d_in[3];
    const float* bq = (const float*)d_in[4];
    const float* Wk = (const float*)d_in[5];
    const float* bk = (const float*)d_in[6];
    const float* Wv = (const float*)d_in[7];
    const float* bv = (const float*)d_in[8];
    const float* Wo = (const float*)d_in[9];
    const float* bo = (const float*)d_in[10];
    float* out = (float*)d_out;
    (void)in_sizes; (void)n_in; (void)out_size;

    cudaFuncSetAttribute(gemm_mma,  cudaFuncAttributeMaxDynamicSharedMemorySize, GSM);
    cudaFuncSetAttribute(flash_mma, cudaFuncAttributeMaxDynamicSharedMemorySize, FSM);

    u16 *w, *x, *ph, *pl, *cc;
    cudaGetSymbolAddress((void**)&w,  g_W);
    cudaGetSymbolAddress((void**)&x,  g_X);
    cudaGetSymbolAddress((void**)&ph, g_Ph);
    cudaGetSymbolAddress((void**)&pl, g_Pl);
    cudaGetSymbolAddress((void**)&cc, g_C);

    cvt_h3<<<(int)(MD / (256 * 4)), 256>>>((const float4*)Q, (const float4*)K, (const float4*)V);
    repack_all<<<dim3(2, 32, 32), dim3(32, 8)>>>(Wq, Wk, Wv, Wo);

    // fused 3-way projection GEMM (single-term fp16): z selects Q/K/V
    gemm_mma<<<dim3(DM / 128, MTOT / 128, 3), 256, GSM>>>(
        x, w, bq, bk, bv, nullptr, ph, pl, 1);

    flash_mma<<<dim3(SEQ / 128, NH, BATCH), 256, FSM>>>();

    // output projection (single-term fp16, fp32 out)
    gemm_mma<<<dim3(DM / 128, MTOT / 128, 1), 256, GSM>>>(
        cc, w + 3u * DM * DM, bo, bo, bo, out, nullptr, nullptr, 0);
}